// round 11
// baseline (speedup 1.0000x reference)
#include <cuda_runtime.h>
#include <cuda_bf16.h>
#include <cstdint>

#define VOCAB 50257
#define BATCH 512
#define SEQ   512

// Single launch, no pack table. One CTA per row, 128 threads, 4 tokens/thread
// via one int4 load. All 8 weight gathers (4 tokens x 2 classes) are
// independent and front-batched -> ~110 in-flight gathers per SM.
__global__ __launch_bounds__(128) void bow_single_kernel(
    const int* __restrict__ ids,
    const float* __restrict__ W,     // [2, VOCAB] row-major
    const float* __restrict__ bias,  // [2]
    float* __restrict__ out)         // [BATCH, 2]
{
    const int row = blockIdx.x;
    const int t   = threadIdx.x;   // 0..127

    const int4 v = reinterpret_cast<const int4*>(ids + row * SEQ)[t];

    const float* __restrict__ W0 = W;
    const float* __restrict__ W1 = W + VOCAB;

    // 8 independent gathers, front-batched by ptxas (no consumer between them).
    const float a0 = __ldg(W0 + v.x);
    const float b0 = __ldg(W1 + v.x);
    const float a1 = __ldg(W0 + v.y);
    const float b1 = __ldg(W1 + v.y);
    const float a2 = __ldg(W0 + v.z);
    const float b2 = __ldg(W1 + v.z);
    const float a3 = __ldg(W0 + v.w);
    const float b3 = __ldg(W1 + v.w);

    const float m0 = (v.x != 0) ? 1.0f : 0.0f;
    const float m1 = (v.y != 0) ? 1.0f : 0.0f;
    const float m2 = (v.z != 0) ? 1.0f : 0.0f;
    const float m3 = (v.w != 0) ? 1.0f : 0.0f;

    float s0 = fmaf(m0, a0, fmaf(m1, a1, fmaf(m2, a2, m3 * a3)));
    float s1 = fmaf(m0, b0, fmaf(m1, b1, fmaf(m2, b2, m3 * b3)));

    // Warp reduce
    #pragma unroll
    for (int o = 16; o > 0; o >>= 1) {
        s0 += __shfl_xor_sync(0xFFFFFFFFu, s0, o);
        s1 += __shfl_xor_sync(0xFFFFFFFFu, s1, o);
    }

    __shared__ float sm0[4], sm1[4];
    const int wid = t >> 5, lid = t & 31;
    if (lid == 0) { sm0[wid] = s0; sm1[wid] = s1; }
    __syncthreads();

    if (wid == 0 && lid < 4) {
        float r0 = sm0[lid];
        float r1 = sm1[lid];
        #pragma unroll
        for (int o = 2; o > 0; o >>= 1) {
            r0 += __shfl_xor_sync(0x0000000Fu, r0, o);
            r1 += __shfl_xor_sync(0x0000000Fu, r1, o);
        }
        if (lid == 0) {
            out[row * 2 + 0] = r0 + __ldg(bias + 0);
            out[row * 2 + 1] = r1 + __ldg(bias + 1);
        }
    }
}

extern "C" void kernel_launch(void* const* d_in, const int* in_sizes, int n_in,
                              void* d_out, int out_size) {
    const int*   ids  = (const int*)d_in[0];    // [512, 512] int32
    const float* W    = (const float*)d_in[1];  // [2, 50257] float32
    const float* bias = (const float*)d_in[2];  // [2] float32
    float* out = (float*)d_out;                 // [512, 2] float32

    bow_single_kernel<<<BATCH, 128>>>(ids, W, bias, out);
}

// round 12
// speedup vs baseline: 1.0489x; 1.0489x over previous
#include <cuda_runtime.h>
#include <cuda_bf16.h>
#include <cstdint>

#define VOCAB 50257
#define BATCH 512
#define SEQ   512

// Single launch. 256 CTAs x 1024 threads = 262144 threads (all tokens
// resident in one wave, ~86% of thread slots). Each CTA covers 2 rows:
// threads [0,512) -> row 2b, [512,1024) -> row 2b+1. 1 token/thread,
// 2 independent front-batched gathers (W0, W1), branch-free pad mask.
__global__ __launch_bounds__(1024) void bow_single_kernel(
    const int* __restrict__ ids,
    const float* __restrict__ W,     // [2, VOCAB] row-major
    const float* __restrict__ bias,  // [2]
    float* __restrict__ out)         // [BATCH, 2]
{
    const int t    = threadIdx.x;          // 0..1023
    const int half = t >> 9;               // 0 or 1 -> which row in this CTA
    const int row  = (blockIdx.x << 1) | half;
    const int tok  = t & 511;              // token index within the row

    const int id = __ldg(ids + row * SEQ + tok);

    // Two independent gathers (front-batched), masked for pad token 0.
    const float a = __ldg(W + id);
    const float b = __ldg(W + VOCAB + id);
    const float m = (id != 0) ? 1.0f : 0.0f;
    float s0 = m * a;
    float s1 = m * b;

    // Warp reduce (each warp is entirely within one row: 512 = 16 warps/row)
    #pragma unroll
    for (int o = 16; o > 0; o >>= 1) {
        s0 += __shfl_xor_sync(0xFFFFFFFFu, s0, o);
        s1 += __shfl_xor_sync(0xFFFFFFFFu, s1, o);
    }

    // 32 warp partials per CTA (16 per row), keyed by warp id.
    __shared__ float sm0[32], sm1[32];
    const int wid = t >> 5, lid = t & 31;
    if (lid == 0) { sm0[wid] = s0; sm1[wid] = s1; }
    __syncthreads();

    // Warp 0 reduces row-0 partials (sm[0..15]); warp 16 reduces row-1
    // partials (sm[16..31]).
    if ((wid == 0 || wid == 16) && lid < 16) {
        float r0 = sm0[wid + lid];
        float r1 = sm1[wid + lid];
        #pragma unroll
        for (int o = 8; o > 0; o >>= 1) {
            r0 += __shfl_xor_sync(0x0000FFFFu, r0, o);
            r1 += __shfl_xor_sync(0x0000FFFFu, r1, o);
        }
        if (lid == 0) {
            const int r = (blockIdx.x << 1) | (wid >> 4);
            out[r * 2 + 0] = r0 + __ldg(bias + 0);
            out[r * 2 + 1] = r1 + __ldg(bias + 1);
        }
    }
}

extern "C" void kernel_launch(void* const* d_in, const int* in_sizes, int n_in,
                              void* d_out, int out_size) {
    const int*   ids  = (const int*)d_in[0];    // [512, 512] int32
    const float* W    = (const float*)d_in[1];  // [2, 50257] float32
    const float* bias = (const float*)d_in[2];  // [2] float32
    float* out = (float*)d_out;                 // [512, 2] float32

    bow_single_kernel<<<BATCH / 2, 1024>>>(ids, W, bias, out);
}